// round 2
// baseline (speedup 1.0000x reference)
#include <cuda_runtime.h>
#include <cuda_fp16.h>
#include <cstdint>

// Problem constants
#define NTRI 32
#define TSTEPS 512
#define IDIM 64
#define NN 4096
#define RR 8
#define ODIM 64
#define DT 0.1f

// x_seq elements: 32 * 513 * 4096
#define XSEQ_ELEMS (32ll * 513 * 4096)

// Scratch: inp_proj [b][t][j] : 32*512*4096 floats = 268 MB
__device__ float g_uproj[(size_t)NTRI * TSTEPS * NN];

__device__ __forceinline__ float sigmoid_fast(float x) {
    float t;
    asm("tanh.approx.f32 %0, %1;" : "=f"(t) : "f"(0.5f * x));
    return fmaf(0.5f, t, 0.5f);
}

// ---------------------------------------------------------------------------
// Kernel 1: inp_proj[b][t][j] = sum_i inp[b][t][i] * B[j][i]
// M = 16384 (b*t), N = 4096 (j), K = 64
// CTA tile: 128 bt x 64 j, 256 threads, thread tile 8bt x 4j, K in 2 chunks of 32
// ---------------------------------------------------------------------------
__global__ void __launch_bounds__(256) proj_kernel(const float* __restrict__ inp,
                                                   const float* __restrict__ B) {
    __shared__ float a_s[32][132];  // [k][bt]
    __shared__ float b_s[32][68];   // [k][j]

    const int tid = threadIdx.x;
    const int g0 = blockIdx.y * 128;   // bt base
    const int jb0 = blockIdx.x * 64;   // j base
    const int ty = tid >> 4;           // 0..15
    const int tx = tid & 15;           // 0..15
    const int bt0 = ty * 8;
    const int j0 = tx * 4;

    float acc[8][4];
#pragma unroll
    for (int i = 0; i < 8; i++)
#pragma unroll
        for (int j = 0; j < 4; j++) acc[i][j] = 0.f;

#pragma unroll
    for (int kc = 0; kc < 2; kc++) {
        if (kc) __syncthreads();
        // load inp tile [128 bt][32 k] -> a_s[k][bt]
#pragma unroll
        for (int it = 0; it < 4; it++) {
            int q = tid + it * 256;
            int r = q >> 3;
            int c4 = q & 7;
            float4 av = *(const float4*)(inp + (size_t)(g0 + r) * 64 + kc * 32 + c4 * 4);
            a_s[c4 * 4 + 0][r] = av.x;
            a_s[c4 * 4 + 1][r] = av.y;
            a_s[c4 * 4 + 2][r] = av.z;
            a_s[c4 * 4 + 3][r] = av.w;
        }
        // load B tile [64 j][32 k] -> b_s[k][j]
#pragma unroll
        for (int it = 0; it < 2; it++) {
            int q = tid + it * 256;
            int jr = q >> 3;
            int c4 = q & 7;
            float4 bv = *(const float4*)(B + (size_t)(jb0 + jr) * 64 + kc * 32 + c4 * 4);
            b_s[c4 * 4 + 0][jr] = bv.x;
            b_s[c4 * 4 + 1][jr] = bv.y;
            b_s[c4 * 4 + 2][jr] = bv.z;
            b_s[c4 * 4 + 3][jr] = bv.w;
        }
        __syncthreads();
#pragma unroll
        for (int k = 0; k < 32; k++) {
            float4 a0 = *(const float4*)&a_s[k][bt0];
            float4 a1 = *(const float4*)&a_s[k][bt0 + 4];
            float4 bb = *(const float4*)&b_s[k][j0];
            float af[8] = {a0.x, a0.y, a0.z, a0.w, a1.x, a1.y, a1.z, a1.w};
            float bf[4] = {bb.x, bb.y, bb.z, bb.w};
#pragma unroll
            for (int i = 0; i < 8; i++)
#pragma unroll
                for (int j = 0; j < 4; j++) acc[i][j] = fmaf(af[i], bf[j], acc[i][j]);
        }
    }
    // epilogue
#pragma unroll
    for (int i = 0; i < 8; i++) {
        float4 o = make_float4(acc[i][0], acc[i][1], acc[i][2], acc[i][3]);
        *(float4*)(g_uproj + (size_t)(g0 + bt0 + i) * NN + jb0 + j0) = o;
    }
}

// ---------------------------------------------------------------------------
// Kernel 2: the recurrence. One CTA per trial, 512 threads, 8 rows/thread.
// x, s in registers; n, m as packed fp16 pairs (fp32 accumulation).
// Rank-8 reduction via folded warp shuffles + 2-stage smem.
// ---------------------------------------------------------------------------
__global__ void __launch_bounds__(512, 1) rnn_scan_kernel(const float* __restrict__ mg,
                                                          const float* __restrict__ ng,
                                                          float* __restrict__ xseq) {
    const int b = blockIdx.x;
    const int tid = threadIdx.x;
    const int j0 = tid * 8;
    const unsigned lane = tid & 31;
    const unsigned warp = tid >> 5;

    __shared__ float vs[8][33];
    __shared__ float vtot[8];

    // zero-init the unwritten tail of vs so the 32-lane reduce is exact
    if (tid < 8 * 33) ((float*)vs)[tid] = 0.f;

    // load n, m rows (8 each) as packed fp16 pairs (10-bit mantissa: rel err 2^-12)
    __half2 nP[8][4], mP[8][4];
#pragma unroll
    for (int k = 0; k < 8; k++) {
        const float* nr = ng + (size_t)(j0 + k) * RR;
        const float* mr = mg + (size_t)(j0 + k) * RR;
#pragma unroll
        for (int p = 0; p < 4; p++) {
            nP[k][p] = __floats2half2_rn(nr[2 * p], nr[2 * p + 1]);
            mP[k][p] = __floats2half2_rn(mr[2 * p], mr[2 * p + 1]);
        }
    }

    float x[8], s[8];
#pragma unroll
    for (int k = 0; k < 8; k++) {
        x[k] = 0.f;
        s[k] = 0.5f;  // sigmoid(0)
    }

    float* xrow0 = xseq + (size_t)b * 513 * NN;
    // x_seq[b][0][:] = 0
    float4 z4 = make_float4(0.f, 0.f, 0.f, 0.f);
    *(float4*)(xrow0 + j0) = z4;
    *(float4*)(xrow0 + j0 + 4) = z4;

    const float* up = g_uproj + (size_t)b * TSTEPS * NN + j0;
    const int my_r = ((lane >> 4) & 1) * 4 + ((lane >> 3) & 1) * 2 + ((lane >> 2) & 1);
    const float keep = 1.0f - DT;

    __syncthreads();  // vs tail zero-init visible before first reduce

    for (int t = 0; t < TSTEPS; t++) {
        // prefetch u for this step (used late; overlaps the reduction)
        const float4 u0 = __ldg((const float4*)(up + (size_t)t * NN));
        const float4 u1 = __ldg((const float4*)(up + (size_t)t * NN + 4));

        // v[r] = sum over my 8 rows of s_j * n[j][r]
        float v[8];
#pragma unroll
        for (int r = 0; r < 8; r++) v[r] = 0.f;
#pragma unroll
        for (int k = 0; k < 8; k++) {
#pragma unroll
            for (int p = 0; p < 4; p++) {
                float2 nf = __half22float2(nP[k][p]);
                v[2 * p] = fmaf(s[k], nf.x, v[2 * p]);
                v[2 * p + 1] = fmaf(s[k], nf.y, v[2 * p + 1]);
            }
        }
        // folded warp reduce: 8 values over 32 lanes
        {
            bool s4 = (lane & 16) != 0;
#pragma unroll
            for (int i = 0; i < 4; i++) {
                float snd = s4 ? v[i] : v[i + 4];
                float rcv = __shfl_xor_sync(0xffffffffu, snd, 16);
                v[i] = (s4 ? v[i + 4] : v[i]) + rcv;
            }
            bool s3 = (lane & 8) != 0;
#pragma unroll
            for (int i = 0; i < 2; i++) {
                float snd = s3 ? v[i] : v[i + 2];
                float rcv = __shfl_xor_sync(0xffffffffu, snd, 8);
                v[i] = (s3 ? v[i + 2] : v[i]) + rcv;
            }
            bool s2 = (lane & 4) != 0;
            {
                float snd = s2 ? v[0] : v[1];
                float rcv = __shfl_xor_sync(0xffffffffu, snd, 4);
                v[0] = (s2 ? v[1] : v[0]) + rcv;
            }
            v[0] += __shfl_xor_sync(0xffffffffu, v[0], 2);
            v[0] += __shfl_xor_sync(0xffffffffu, v[0], 1);
        }
        if ((lane & 3) == 0) vs[my_r][warp] = v[0];
        __syncthreads();
        if (warp < 8) {
            float val = vs[warp][lane];  // lanes 16..31 read the zero-initialized tail
#pragma unroll
            for (int d = 16; d > 0; d >>= 1) val += __shfl_xor_sync(0xffffffffu, val, d);
            if (lane == 0) vtot[warp] = val;
        }
        __syncthreads();

        float4 vv0 = *(const float4*)&vtot[0];
        float4 vv1 = *(const float4*)&vtot[4];
        float vvv[8] = {vv0.x, vv0.y, vv0.z, vv0.w, vv1.x, vv1.y, vv1.z, vv1.w};
        float ua[8] = {u0.x, u0.y, u0.z, u0.w, u1.x, u1.y, u1.z, u1.w};

#pragma unroll
        for (int k = 0; k < 8; k++) {
            float rec = 0.f;
#pragma unroll
            for (int p = 0; p < 4; p++) {
                float2 mf = __half22float2(mP[k][p]);
                rec = fmaf(vvv[2 * p], mf.x, rec);
                rec = fmaf(vvv[2 * p + 1], mf.y, rec);
            }
            float drive = fmaf(rec, (1.0f / (float)NN), ua[k]);
            x[k] = fmaf(keep, x[k], DT * drive);
            s[k] = sigmoid_fast(x[k]);
        }

        float* dst = xrow0 + (size_t)(t + 1) * NN + j0;
        *(float4*)dst = make_float4(x[0], x[1], x[2], x[3]);
        *(float4*)(dst + 4) = make_float4(x[4], x[5], x[6], x[7]);
    }
}

// ---------------------------------------------------------------------------
// Kernel 3: y[b][t][o] = sum_j sigmoid(x_seq[b][t+1][j]) * W[o][j]
// M = 16384 (bt), N = 64 (o), K = 4096 in chunks of 32
// CTA tile: 64 bt x 64 o, 256 threads, thread tile 4bt x 4o
// ---------------------------------------------------------------------------
__global__ void __launch_bounds__(256) out_kernel(const float* __restrict__ xseq,
                                                  const float* __restrict__ W,
                                                  float* __restrict__ out2) {
    __shared__ float x_s[32][68];  // [k][bt], sigmoid already applied
    __shared__ float w_s[32][68];  // [k][o]

    const int tid = threadIdx.x;
    const int g0 = blockIdx.x * 64;  // bt base (stays within one trial: 64 | 512)
    const int bb = g0 >> 9;
    const int t0 = g0 & 511;
    const float* xbase = xseq + (size_t)bb * 513 * NN + (size_t)(t0 + 1) * NN;

    const int ty = tid >> 4;
    const int tx = tid & 15;
    const int bt0 = ty * 4;
    const int o0 = tx * 4;

    float acc[4][4];
#pragma unroll
    for (int i = 0; i < 4; i++)
#pragma unroll
        for (int j = 0; j < 4; j++) acc[i][j] = 0.f;

    for (int kc = 0; kc < NN / 32; kc++) {
        if (kc) __syncthreads();
        // x tile: [64 bt][32 k] -> sigmoid -> x_s[k][bt]
#pragma unroll
        for (int it = 0; it < 2; it++) {
            int q = tid + it * 256;
            int r = q >> 3;
            int c4 = q & 7;
            float4 xv = *(const float4*)(xbase + (size_t)r * NN + kc * 32 + c4 * 4);
            float s0 = 1.0f / (1.0f + __expf(-xv.x));
            float s1 = 1.0f / (1.0f + __expf(-xv.y));
            float s2 = 1.0f / (1.0f + __expf(-xv.z));
            float s3 = 1.0f / (1.0f + __expf(-xv.w));
            x_s[c4 * 4 + 0][r] = s0;
            x_s[c4 * 4 + 1][r] = s1;
            x_s[c4 * 4 + 2][r] = s2;
            x_s[c4 * 4 + 3][r] = s3;
        }
        // W tile: [64 o][32 k] -> w_s[k][o]
#pragma unroll
        for (int it = 0; it < 2; it++) {
            int q = tid + it * 256;
            int o = q >> 3;
            int c4 = q & 7;
            float4 wv = *(const float4*)(W + (size_t)o * NN + kc * 32 + c4 * 4);
            w_s[c4 * 4 + 0][o] = wv.x;
            w_s[c4 * 4 + 1][o] = wv.y;
            w_s[c4 * 4 + 2][o] = wv.z;
            w_s[c4 * 4 + 3][o] = wv.w;
        }
        __syncthreads();
#pragma unroll
        for (int k = 0; k < 32; k++) {
            float4 a = *(const float4*)&x_s[k][bt0];
            float4 w4 = *(const float4*)&w_s[k][o0];
            float af[4] = {a.x, a.y, a.z, a.w};
            float wf[4] = {w4.x, w4.y, w4.z, w4.w};
#pragma unroll
            for (int i = 0; i < 4; i++)
#pragma unroll
                for (int j = 0; j < 4; j++) acc[i][j] = fmaf(af[i], wf[j], acc[i][j]);
        }
    }
#pragma unroll
    for (int i = 0; i < 4; i++) {
        float4 o = make_float4(acc[i][0], acc[i][1], acc[i][2], acc[i][3]);
        *(float4*)(out2 + (size_t)(g0 + bt0 + i) * ODIM + o0) = o;
    }
}

// ---------------------------------------------------------------------------
extern "C" void kernel_launch(void* const* d_in, const int* in_sizes, int n_in,
                              void* d_out, int out_size) {
    const float* inp = (const float*)d_in[0];  // [32,512,64]
    const float* B = (const float*)d_in[1];    // [4096,64]
    const float* W = (const float*)d_in[2];    // [64,4096]
    const float* m = (const float*)d_in[3];    // [4096,8]
    const float* n = (const float*)d_in[4];    // [4096,8]

    float* xseq = (float*)d_out;               // [32,513,4096]
    float* out2 = (float*)d_out + XSEQ_ELEMS;  // [32,512,64]

    // 1) input projection
    {
        dim3 grid(NN / 64, (NTRI * TSTEPS) / 128);
        proj_kernel<<<grid, 256>>>(inp, B);
    }
    // 2) recurrence scan
    rnn_scan_kernel<<<NTRI, 512>>>(m, n, xseq);
    // 3) output projection
    out_kernel<<<(NTRI * TSTEPS) / 64, 256>>>(xseq, W, out2);
}

// round 4
// speedup vs baseline: 1.7320x; 1.7320x over previous
#include <cuda_runtime.h>
#include <cuda_fp16.h>
#include <cstdint>

// Problem constants
#define NTRI 32
#define TSTEPS 512
#define IDIM 64
#define NN 4096
#define RR 8
#define ODIM 64
#define DT 0.1f

#define XSEQ_ELEMS (32ll * 513 * 4096)

// Scratch: inp_proj [b][t][j] : 32*512*4096 floats = 268 MB
__device__ float g_uproj[(size_t)NTRI * TSTEPS * NN];

__device__ __forceinline__ float sigmoid_fast(float x) {
    float t;
    asm("tanh.approx.f32 %0, %1;" : "=f"(t) : "f"(0.5f * x));
    return fmaf(0.5f, t, 0.5f);
}

__device__ __forceinline__ void red_shared_f32(float* p, float v) {
    unsigned addr = (unsigned)__cvta_generic_to_shared(p);
    asm volatile("red.shared.add.f32 [%0], %1;" :: "r"(addr), "f"(v) : "memory");
}

__device__ __forceinline__ __half2 shfl_xor_h2(__half2 v, int m) {
    unsigned u = *reinterpret_cast<unsigned*>(&v);
    u = __shfl_xor_sync(0xffffffffu, u, m);
    return *reinterpret_cast<__half2*>(&u);
}

// ---------------------------------------------------------------------------
// Kernel 1: inp_proj[b][t][j] = sum_i inp[b][t][i] * B[j][i]
// ---------------------------------------------------------------------------
__global__ void __launch_bounds__(256) proj_kernel(const float* __restrict__ inp,
                                                   const float* __restrict__ B) {
    __shared__ float a_s[32][132];  // [k][bt]
    __shared__ float b_s[32][68];   // [k][j]

    const int tid = threadIdx.x;
    const int g0 = blockIdx.y * 128;   // bt base
    const int jb0 = blockIdx.x * 64;   // j base
    const int ty = tid >> 4;
    const int tx = tid & 15;
    const int bt0 = ty * 8;
    const int j0 = tx * 4;

    float acc[8][4];
#pragma unroll
    for (int i = 0; i < 8; i++)
#pragma unroll
        for (int j = 0; j < 4; j++) acc[i][j] = 0.f;

#pragma unroll
    for (int kc = 0; kc < 2; kc++) {
        if (kc) __syncthreads();
#pragma unroll
        for (int it = 0; it < 4; it++) {
            int q = tid + it * 256;
            int r = q >> 3;
            int c4 = q & 7;
            float4 av = *(const float4*)(inp + (size_t)(g0 + r) * 64 + kc * 32 + c4 * 4);
            a_s[c4 * 4 + 0][r] = av.x;
            a_s[c4 * 4 + 1][r] = av.y;
            a_s[c4 * 4 + 2][r] = av.z;
            a_s[c4 * 4 + 3][r] = av.w;
        }
#pragma unroll
        for (int it = 0; it < 2; it++) {
            int q = tid + it * 256;
            int jr = q >> 3;
            int c4 = q & 7;
            float4 bv = *(const float4*)(B + (size_t)(jb0 + jr) * 64 + kc * 32 + c4 * 4);
            b_s[c4 * 4 + 0][jr] = bv.x;
            b_s[c4 * 4 + 1][jr] = bv.y;
            b_s[c4 * 4 + 2][jr] = bv.z;
            b_s[c4 * 4 + 3][jr] = bv.w;
        }
        __syncthreads();
#pragma unroll
        for (int k = 0; k < 32; k++) {
            float4 a0 = *(const float4*)&a_s[k][bt0];
            float4 a1 = *(const float4*)&a_s[k][bt0 + 4];
            float4 bb = *(const float4*)&b_s[k][j0];
            float af[8] = {a0.x, a0.y, a0.z, a0.w, a1.x, a1.y, a1.z, a1.w};
            float bf[4] = {bb.x, bb.y, bb.z, bb.w};
#pragma unroll
            for (int i = 0; i < 8; i++)
#pragma unroll
                for (int j = 0; j < 4; j++) acc[i][j] = fmaf(af[i], bf[j], acc[i][j]);
        }
    }
#pragma unroll
    for (int i = 0; i < 8; i++) {
        float4 o = make_float4(acc[i][0], acc[i][1], acc[i][2], acc[i][3]);
        *(float4*)(g_uproj + (size_t)(g0 + bt0 + i) * NN + jb0 + j0) = o;
    }
}

// ---------------------------------------------------------------------------
// Kernel 2: recurrence. One CTA per trial, 512 threads, 8 neurons/thread.
// half2 math; single barrier/step; red.shared rank-8 accumulation with
// 4-way rotated buffers; u prefetched one full step ahead.
// ---------------------------------------------------------------------------
__global__ void __launch_bounds__(512, 1) rnn_scan_kernel(const float* __restrict__ mg,
                                                          const float* __restrict__ ng,
                                                          float* __restrict__ xseq) {
    const int b = blockIdx.x;
    const int tid = threadIdx.x;
    const int j0 = tid * 8;
    const unsigned lane = tid & 31;

    __shared__ float vtot[4][8];

    // load n, m rows as packed fp16 pairs; m pre-scaled by DT
    __half2 nP[8][4], mP[8][4];
#pragma unroll
    for (int k = 0; k < 8; k++) {
        const float* nr = ng + (size_t)(j0 + k) * RR;
        const float* mr = mg + (size_t)(j0 + k) * RR;
#pragma unroll
        for (int p = 0; p < 4; p++) {
            nP[k][p] = __floats2half2_rn(nr[2 * p], nr[2 * p + 1]);
            mP[k][p] = __floats2half2_rn(mr[2 * p] * DT, mr[2 * p + 1] * DT);
        }
    }

    float x[8];
    __half2 sd[8];
    const __half2 half05 = __floats2half2_rn(0.5f, 0.5f);
#pragma unroll
    for (int k = 0; k < 8; k++) {
        x[k] = 0.f;
        sd[k] = half05;
    }

    if (tid < 32) ((float*)vtot)[tid] = 0.f;

    float* xrow0 = xseq + (size_t)b * 513 * NN;
    float4 z4 = make_float4(0.f, 0.f, 0.f, 0.f);
    *(float4*)(xrow0 + j0) = z4;
    *(float4*)(xrow0 + j0 + 4) = z4;

    const float* up = g_uproj + (size_t)b * TSTEPS * NN + j0;
    const float keep = 1.0f - DT;
    const float invN = 1.0f / (float)NN;
    const int q = ((lane >> 4) & 1) * 2 + ((lane >> 3) & 1);
    const bool hi16 = (lane & 16) != 0;
    const bool hi8 = (lane & 8) != 0;

    __syncthreads();

    // prefetch u for step 0
    float4 u0 = __ldg((const float4*)up);
    float4 u1 = __ldg((const float4*)(up + 4));

    for (int t = 0; t < TSTEPS; t++) {
        // prefetch u for step t+1 (consumed one full step later)
        float4 p0, p1;
        if (t + 1 < TSTEPS) {
            p0 = __ldg((const float4*)(up + (size_t)(t + 1) * NN));
            p1 = __ldg((const float4*)(up + (size_t)(t + 1) * NN + 4));
        } else {
            p0 = z4; p1 = z4;
        }

        // v partials in half2: h[q] = (v[2q], v[2q+1]) contribution of my 8 rows
        __half2 h[4];
#pragma unroll
        for (int p = 0; p < 4; p++) h[p] = __floats2half2_rn(0.f, 0.f);
#pragma unroll
        for (int k = 0; k < 8; k++) {
#pragma unroll
            for (int p = 0; p < 4; p++) h[p] = __hfma2(sd[k], nP[k][p], h[p]);
        }

        // folded warp reduce: 4 half2 regs over 32 lanes -> 1 half2 per 8-lane group
#pragma unroll
        for (int p = 0; p < 2; p++) {
            __half2 snd = hi16 ? h[p] : h[p + 2];
            __half2 rcv = shfl_xor_h2(snd, 16);
            h[p] = __hadd2(hi16 ? h[p + 2] : h[p], rcv);
        }
        {
            __half2 snd = hi8 ? h[0] : h[1];
            __half2 rcv = shfl_xor_h2(snd, 8);
            h[0] = __hadd2(hi8 ? h[1] : h[0], rcv);
        }
        h[0] = __hadd2(h[0], shfl_xor_h2(h[0], 4));
        h[0] = __hadd2(h[0], shfl_xor_h2(h[0], 2));
        h[0] = __hadd2(h[0], shfl_xor_h2(h[0], 1));

        const int cur = t & 3;
        if ((lane & 7) == 0) {
            float2 vf = __half22float2(h[0]);
            red_shared_f32(&vtot[cur][2 * q], vf.x);
            red_shared_f32(&vtot[cur][2 * q + 1], vf.y);
        }
        // zero the buffer for step t+1 (its readers finished >= 2 barriers ago)
        if (tid < 8) vtot[(t + 1) & 3][tid] = 0.f;
        __syncthreads();

        float4 va = *(const float4*)&vtot[cur][0];
        float4 vb = *(const float4*)&vtot[cur][4];
        __half2 vh[4];
        vh[0] = __floats2half2_rn(va.x * invN, va.y * invN);
        vh[1] = __floats2half2_rn(va.z * invN, va.w * invN);
        vh[2] = __floats2half2_rn(vb.x * invN, vb.y * invN);
        vh[3] = __floats2half2_rn(vb.z * invN, vb.w * invN);

        float ua[8] = {u0.x, u0.y, u0.z, u0.w, u1.x, u1.y, u1.z, u1.w};

#pragma unroll
        for (int k = 0; k < 8; k++) {
            __half2 rh = __hmul2(vh[0], mP[k][0]);
            rh = __hfma2(vh[1], mP[k][1], rh);
            rh = __hfma2(vh[2], mP[k][2], rh);
            rh = __hfma2(vh[3], mP[k][3], rh);
            float rec = __low2float(rh) + __high2float(rh);  // already scaled by DT
            x[k] = fmaf(keep, x[k], fmaf(DT, ua[k], rec));
            float s = sigmoid_fast(x[k]);
            sd[k] = __half2half2(__float2half_rn(s));
        }

        float* dst = xrow0 + (size_t)(t + 1) * NN + j0;
        *(float4*)dst = make_float4(x[0], x[1], x[2], x[3]);
        *(float4*)(dst + 4) = make_float4(x[4], x[5], x[6], x[7]);

        u0 = p0; u1 = p1;
    }
}

// ---------------------------------------------------------------------------
// Kernel 3: y[b][t][o] = sum_j sigmoid(x_seq[b][t+1][j]) * W[o][j]
// ---------------------------------------------------------------------------
__global__ void __launch_bounds__(256) out_kernel(const float* __restrict__ xseq,
                                                  const float* __restrict__ W,
                                                  float* __restrict__ out2) {
    __shared__ float x_s[32][68];
    __shared__ float w_s[32][68];

    const int tid = threadIdx.x;
    const int g0 = blockIdx.x * 64;
    const int bb = g0 >> 9;
    const int t0 = g0 & 511;
    const float* xbase = xseq + (size_t)bb * 513 * NN + (size_t)(t0 + 1) * NN;

    const int ty = tid >> 4;
    const int tx = tid & 15;
    const int bt0 = ty * 4;
    const int o0 = tx * 4;

    float acc[4][4];
#pragma unroll
    for (int i = 0; i < 4; i++)
#pragma unroll
        for (int j = 0; j < 4; j++) acc[i][j] = 0.f;

    for (int kc = 0; kc < NN / 32; kc++) {
        if (kc) __syncthreads();
#pragma unroll
        for (int it = 0; it < 2; it++) {
            int q = tid + it * 256;
            int r = q >> 3;
            int c4 = q & 7;
            float4 xv = *(const float4*)(xbase + (size_t)r * NN + kc * 32 + c4 * 4);
            x_s[c4 * 4 + 0][r] = sigmoid_fast(xv.x);
            x_s[c4 * 4 + 1][r] = sigmoid_fast(xv.y);
            x_s[c4 * 4 + 2][r] = sigmoid_fast(xv.z);
            x_s[c4 * 4 + 3][r] = sigmoid_fast(xv.w);
        }
#pragma unroll
        for (int it = 0; it < 2; it++) {
            int q = tid + it * 256;
            int o = q >> 3;
            int c4 = q & 7;
            float4 wv = *(const float4*)(W + (size_t)o * NN + kc * 32 + c4 * 4);
            w_s[c4 * 4 + 0][o] = wv.x;
            w_s[c4 * 4 + 1][o] = wv.y;
            w_s[c4 * 4 + 2][o] = wv.z;
            w_s[c4 * 4 + 3][o] = wv.w;
        }
        __syncthreads();
#pragma unroll
        for (int k = 0; k < 32; k++) {
            float4 a = *(const float4*)&x_s[k][bt0];
            float4 w4 = *(const float4*)&w_s[k][o0];
            float af[4] = {a.x, a.y, a.z, a.w};
            float wf[4] = {w4.x, w4.y, w4.z, w4.w};
#pragma unroll
            for (int i = 0; i < 4; i++)
#pragma unroll
                for (int j = 0; j < 4; j++) acc[i][j] = fmaf(af[i], wf[j], acc[i][j]);
        }
    }
#pragma unroll
    for (int i = 0; i < 4; i++) {
        float4 o = make_float4(acc[i][0], acc[i][1], acc[i][2], acc[i][3]);
        *(float4*)(out2 + (size_t)(g0 + bt0 + i) * ODIM + o0) = o;
    }
}

// ---------------------------------------------------------------------------
extern "C" void kernel_launch(void* const* d_in, const int* in_sizes, int n_in,
                              void* d_out, int out_size) {
    const float* inp = (const float*)d_in[0];  // [32,512,64]
    const float* B = (const float*)d_in[1];    // [4096,64]
    const float* W = (const float*)d_in[2];    // [64,4096]
    const float* m = (const float*)d_in[3];    // [4096,8]
    const float* n = (const float*)d_in[4];    // [4096,8]

    float* xseq = (float*)d_out;               // [32,513,4096]
    float* out2 = (float*)d_out + XSEQ_ELEMS;  // [32,512,64]

    {
        dim3 grid(NN / 64, (NTRI * TSTEPS) / 128);
        proj_kernel<<<grid, 256>>>(inp, B);
    }
    rnn_scan_kernel<<<NTRI, 512>>>(m, n, xseq);
    out_kernel<<<(NTRI * TSTEPS) / 64, 256>>>(xseq, W, out2);
}